// round 4
// baseline (speedup 1.0000x reference)
#include <cuda_runtime.h>

// InnerProduct: ip[r,p] = sum_f w[p,f]^2 * sum_e x[r,f,e]^2
// x: [32768, 64, 128] f32, w: [10, 64] f32, out: [32768, 10] f32
//
// DRAM-bound (1 GiB read of x), running at ~92% of HBM spec. This version
// removes ALL inter-warp coupling: no smem, no __syncthreads. Each warp owns
// 8 fields of one row, reduces them with a 9-SHFL fold, gathers with 8 SHFLs,
// and lanes 0..9 each REDG-accumulate one output's partial contribution.
// Warps retire as soon as their own loads complete. d_out is zero-initialized
// by a cudaMemsetAsync node in the same graph.

#define BATCH    32768
#define N_FIELDS 64
#define EMBED    128
#define OUT_SZ   10
#define THREADS  256

__global__ __launch_bounds__(THREADS)
void innerproduct_kernel(const float* __restrict__ x,
                         const float* __restrict__ w,
                         float* __restrict__ out)
{
    const int row  = blockIdx.x;
    const int warp = threadIdx.x >> 5;   // field group 0..7
    const int lane = threadIdx.x & 31;

    // Warp owns fields warp*8 .. warp*8+7 (contiguous 4KB of the row).
    const float4* __restrict__ xr =
        reinterpret_cast<const float4*>(x)
        + (size_t)row * (N_FIELDS * EMBED / 4) + warp * 8 * (EMBED / 4);

    // Front-batched: 8 independent LDG.128 per thread.
    float4 vv[8];
#pragma unroll
    for (int i = 0; i < 8; i++)
        vv[i] = xr[i * (EMBED / 4) + lane];

    // Squared weights for this warp's 8 fields; lane p<10 serves output p.
    // Issued now so their latency hides under the x-load wait.
    float wsq[8];
    if (lane < OUT_SZ) {
#pragma unroll
        for (int k = 0; k < 8; k++) {
            float wv = __ldg(&w[lane * N_FIELDS + warp * 8 + k]);
            wsq[k] = wv * wv;
        }
    }

    float v[8];
#pragma unroll
    for (int i = 0; i < 8; i++)
        v[i] = vv[i].x * vv[i].x + vv[i].y * vv[i].y
             + vv[i].z * vv[i].z + vv[i].w * vv[i].w;

    // Fold-and-split multi-value reduce: 8 values -> 1 per lane in 9 SHFLs.
    // Afterward v[0] on lane l = full 32-lane sum of field warp*8 + ((l>>2)&7).
    {
        const bool hi16 = (lane & 16) != 0;
#pragma unroll
        for (int j = 0; j < 4; j++) {
            float send = hi16 ? v[j] : v[j + 4];
            float recv = __shfl_xor_sync(0xffffffffu, send, 16);
            v[j] = (hi16 ? v[j + 4] : v[j]) + recv;
        }
        const bool hi8 = (lane & 8) != 0;
#pragma unroll
        for (int j = 0; j < 2; j++) {
            float send = hi8 ? v[j] : v[j + 2];
            float recv = __shfl_xor_sync(0xffffffffu, send, 8);
            v[j] = (hi8 ? v[j + 2] : v[j]) + recv;
        }
        const bool hi4 = (lane & 4) != 0;
        {
            float send = hi4 ? v[0] : v[1];
            float recv = __shfl_xor_sync(0xffffffffu, send, 4);
            v[0] = (hi4 ? v[1] : v[0]) + recv;
        }
        v[0] += __shfl_xor_sync(0xffffffffu, v[0], 2);
        v[0] += __shfl_xor_sync(0xffffffffu, v[0], 1);
    }

    // Broadcast-gather the 8 field sums to every lane (lane 4k holds field k).
    float xs[8];
#pragma unroll
    for (int k = 0; k < 8; k++)
        xs[k] = __shfl_sync(0xffffffffu, v[0], k * 4);

    // Lane p<10: partial dot for output p over this warp's 8 fields, then
    // accumulate into global (REDG; out pre-zeroed by memset node).
    if (lane < OUT_SZ) {
        float s = 0.f;
#pragma unroll
        for (int k = 0; k < 8; k++)
            s = fmaf(xs[k], wsq[k], s);
        atomicAdd(&out[row * OUT_SZ + lane], s);
    }
}

extern "C" void kernel_launch(void* const* d_in, const int* in_sizes, int n_in,
                              void* d_out, int out_size)
{
    const float* x = (const float*)d_in[0];
    const float* w = (const float*)d_in[1];
    float* out = (float*)d_out;

    cudaMemsetAsync(d_out, 0, (size_t)out_size * sizeof(float), 0);
    innerproduct_kernel<<<BATCH, THREADS>>>(x, w, out);
}

// round 6
// speedup vs baseline: 1.0275x; 1.0275x over previous
#include <cuda_runtime.h>

// InnerProduct: ip[r,p] = sum_f w[p,f]^2 * sum_e x[r,f,e]^2
// x: [32768, 64, 128] f32, w: [10, 64] f32, out: [32768, 10] f32
//
// DRAM-bound (1 GiB read of x) at ~92% of HBM spec. R3 structure (one-shot
// CTA/row, 8 warps x 8 fields, fold-reduce, tiny smem tail), with the 8
// LDG.128 per thread split into two batches of 4. Halving the front-batched
// load count (MLP_p1 8 -> 4) reduces cross-CTA L1tex-queue contention /
// CTA-completion spread at occ=8 while keeping DRAM saturated, and caps live
// float4 registers at 4 so regs stay <= 32 (8 CTAs/SM).

#define BATCH    32768
#define N_FIELDS 64
#define EMBED    128
#define OUT_SZ   10
#define THREADS  256

__global__ __launch_bounds__(THREADS)
void innerproduct_kernel(const float* __restrict__ x,
                         const float* __restrict__ w,
                         float* __restrict__ out)
{
    const int r    = blockIdx.x;
    const int tid  = threadIdx.x;
    const int warp = tid >> 5;
    const int lane = tid & 31;

    __shared__ float xsq[N_FIELDS];

    // Warp owns fields warp*8 .. warp*8+7 (contiguous 4KB of the row).
    const float4* __restrict__ xr =
        reinterpret_cast<const float4*>(x)
        + (size_t)r * (N_FIELDS * EMBED / 4) + warp * 8 * (EMBED / 4) + lane;

    float v[8];

    // Batch 1: 4 independent LDG.128.
    float4 a0 = xr[0 * (EMBED / 4)];
    float4 a1 = xr[1 * (EMBED / 4)];
    float4 a2 = xr[2 * (EMBED / 4)];
    float4 a3 = xr[3 * (EMBED / 4)];

    // Weight loads for the tail issue here (latency hidden under x loads).
    const int p = tid >> 4;   // output 0..9 for tid < 160
    const int g = tid & 15;   // owns fields g*4..g*4+3
    float wsq[4] = {0.f, 0.f, 0.f, 0.f};
    if (tid < OUT_SZ * 16) {
#pragma unroll
        for (int k = 0; k < 4; k++) {
            float wv = __ldg(&w[p * N_FIELDS + g * 4 + k]);
            wsq[k] = wv * wv;
        }
    }

    v[0] = a0.x * a0.x + a0.y * a0.y + a0.z * a0.z + a0.w * a0.w;
    v[1] = a1.x * a1.x + a1.y * a1.y + a1.z * a1.z + a1.w * a1.w;
    v[2] = a2.x * a2.x + a2.y * a2.y + a2.z * a2.z + a2.w * a2.w;
    v[3] = a3.x * a3.x + a3.y * a3.y + a3.z * a3.z + a3.w * a3.w;

    // Batch 2: next 4 loads (regs of batch 1 now dead).
    float4 b0 = xr[4 * (EMBED / 4)];
    float4 b1 = xr[5 * (EMBED / 4)];
    float4 b2 = xr[6 * (EMBED / 4)];
    float4 b3 = xr[7 * (EMBED / 4)];

    v[4] = b0.x * b0.x + b0.y * b0.y + b0.z * b0.z + b0.w * b0.w;
    v[5] = b1.x * b1.x + b1.y * b1.y + b1.z * b1.z + b1.w * b1.w;
    v[6] = b2.x * b2.x + b2.y * b2.y + b2.z * b2.z + b2.w * b2.w;
    v[7] = b3.x * b3.x + b3.y * b3.y + b3.z * b3.z + b3.w * b3.w;

    // Fold-and-split multi-value warp reduce: 8 -> 1 per lane in 9 SHFLs.
    // Afterward lane l holds the full sum of field warp*8 + ((l>>2)&7).
    {
        const bool hi16 = (lane & 16) != 0;
#pragma unroll
        for (int j = 0; j < 4; j++) {
            float send = hi16 ? v[j] : v[j + 4];
            float recv = __shfl_xor_sync(0xffffffffu, send, 16);
            v[j] = (hi16 ? v[j + 4] : v[j]) + recv;
        }
        const bool hi8 = (lane & 8) != 0;
#pragma unroll
        for (int j = 0; j < 2; j++) {
            float send = hi8 ? v[j] : v[j + 2];
            float recv = __shfl_xor_sync(0xffffffffu, send, 8);
            v[j] = (hi8 ? v[j + 2] : v[j]) + recv;
        }
        const bool hi4 = (lane & 4) != 0;
        {
            float send = hi4 ? v[0] : v[1];
            float recv = __shfl_xor_sync(0xffffffffu, send, 4);
            v[0] = (hi4 ? v[1] : v[0]) + recv;
        }
        v[0] += __shfl_xor_sync(0xffffffffu, v[0], 2);
        v[0] += __shfl_xor_sync(0xffffffffu, v[0], 1);
    }
    if ((lane & 3) == 0)
        xsq[warp * 8 + ((lane >> 2) & 7)] = v[0];
    __syncthreads();

    // Tail: 10 outputs x 16 threads (warps 0..4).
    if (tid < OUT_SZ * 16) {
        float s = 0.f;
#pragma unroll
        for (int k = 0; k < 4; k++)
            s = fmaf(xsq[g * 4 + k], wsq[k], s);
#pragma unroll
        for (int sh = 8; sh >= 1; sh >>= 1)
            s += __shfl_xor_sync(0xffffffffu, s, sh);
        if (g == 0)
            out[r * OUT_SZ + p] = s;
    }
}

extern "C" void kernel_launch(void* const* d_in, const int* in_sizes, int n_in,
                              void* d_out, int out_size)
{
    const float* x = (const float*)d_in[0];
    const float* w = (const float*)d_in[1];
    float* out = (float*)d_out;

    innerproduct_kernel<<<BATCH, THREADS>>>(x, w, out);
}

// round 7
// speedup vs baseline: 1.0415x; 1.0136x over previous
#include <cuda_runtime.h>

// InnerProduct: ip[r,p] = sum_f w[p,f]^2 * sum_e x[r,f,e]^2
// x: [32768, 64, 128] f32, w: [10, 64] f32, out: [32768, 10] f32
//
// DRAM-bound (1 GiB single-pass read of x) at ~92% of HBM spec — the measured
// plateau across three structural variants. R3 structure (one-shot CTA/row,
// 8 warps x 8 fields, 8 front-batched LDG.128/thread, 9-SHFL fold-reduce,
// tiny smem tail) with streaming cache hints: x is strictly single-use, so
// __ldcs (evict-first) lets LTS retire sectors immediately; output uses __stcs.

#define BATCH    32768
#define N_FIELDS 64
#define EMBED    128
#define OUT_SZ   10
#define THREADS  256

__global__ __launch_bounds__(THREADS)
void innerproduct_kernel(const float* __restrict__ x,
                         const float* __restrict__ w,
                         float* __restrict__ out)
{
    const int r    = blockIdx.x;
    const int tid  = threadIdx.x;
    const int warp = tid >> 5;
    const int lane = tid & 31;

    __shared__ float xsq[N_FIELDS];

    // Warp owns fields warp*8 .. warp*8+7 (contiguous 4KB of the row);
    // lane l takes float4 #l of each field. 8 independent LDG.128, streaming.
    const float4* __restrict__ xr =
        reinterpret_cast<const float4*>(x)
        + (size_t)r * (N_FIELDS * EMBED / 4) + warp * 8 * (EMBED / 4) + lane;

    float4 vv[8];
#pragma unroll
    for (int i = 0; i < 8; i++)
        vv[i] = __ldcs(&xr[i * (EMBED / 4)]);

    // Weight loads (reused by every CTA -> default caching) issue now so
    // their latency hides under the x-load wait.
    const int p = tid >> 4;   // output 0..9 for tid < 160
    const int g = tid & 15;   // owns fields g*4..g*4+3
    float wsq[4] = {0.f, 0.f, 0.f, 0.f};
    if (tid < OUT_SZ * 16) {
#pragma unroll
        for (int k = 0; k < 4; k++) {
            float wv = __ldg(&w[p * N_FIELDS + g * 4 + k]);
            wsq[k] = wv * wv;
        }
    }

    float v[8];
#pragma unroll
    for (int i = 0; i < 8; i++)
        v[i] = vv[i].x * vv[i].x + vv[i].y * vv[i].y
             + vv[i].z * vv[i].z + vv[i].w * vv[i].w;

    // Fold-and-split multi-value warp reduce: 8 -> 1 per lane in 9 SHFLs.
    // Afterward lane l holds the full sum of field warp*8 + ((l>>2)&7).
    {
        const bool hi16 = (lane & 16) != 0;
#pragma unroll
        for (int j = 0; j < 4; j++) {
            float send = hi16 ? v[j] : v[j + 4];
            float recv = __shfl_xor_sync(0xffffffffu, send, 16);
            v[j] = (hi16 ? v[j + 4] : v[j]) + recv;
        }
        const bool hi8 = (lane & 8) != 0;
#pragma unroll
        for (int j = 0; j < 2; j++) {
            float send = hi8 ? v[j] : v[j + 2];
            float recv = __shfl_xor_sync(0xffffffffu, send, 8);
            v[j] = (hi8 ? v[j + 2] : v[j]) + recv;
        }
        const bool hi4 = (lane & 4) != 0;
        {
            float send = hi4 ? v[0] : v[1];
            float recv = __shfl_xor_sync(0xffffffffu, send, 4);
            v[0] = (hi4 ? v[1] : v[0]) + recv;
        }
        v[0] += __shfl_xor_sync(0xffffffffu, v[0], 2);
        v[0] += __shfl_xor_sync(0xffffffffu, v[0], 1);
    }
    if ((lane & 3) == 0)
        xsq[warp * 8 + ((lane >> 2) & 7)] = v[0];
    __syncthreads();

    // Tail: 10 outputs x 16 threads (warps 0..4).
    if (tid < OUT_SZ * 16) {
        float s = 0.f;
#pragma unroll
        for (int k = 0; k < 4; k++)
            s = fmaf(xsq[g * 4 + k], wsq[k], s);
#pragma unroll
        for (int sh = 8; sh >= 1; sh >>= 1)
            s += __shfl_xor_sync(0xffffffffu, s, sh);
        if (g == 0)
            __stcs(&out[r * OUT_SZ + p], s);
    }
}

extern "C" void kernel_launch(void* const* d_in, const int* in_sizes, int n_in,
                              void* d_out, int out_size)
{
    const float* x = (const float*)d_in[0];
    const float* w = (const float*)d_in[1];
    float* out = (float*)d_out;

    innerproduct_kernel<<<BATCH, THREADS>>>(x, w, out);
}